// round 1
// baseline (speedup 1.0000x reference)
#include <cuda_runtime.h>
#include <math.h>

#define BB 4
#define KQn 192
#define KPn 192
#define Hn 256
#define Tn 32
#define Rn 768
#define NEGV (-1e9f)
#define SCALEV (0.17677669529663687f)   // 1/sqrt(32)

// ---------------- scratch (static device globals; no runtime allocation) ----------------
static __device__ float g_A1[BB * KQn * Tn];       // Eq @ W1^T
static __device__ float g_A2[BB * KPn * Tn];       // Ep @ W2^T
static __device__ float g_u1[BB * KQn];            // Eq . w_out[0:H]
static __device__ float g_u2[BB * KPn];            // Ep . w_out[H:2H]
static __device__ float g_fq[BB * KPn * KQn * Tn];
static __device__ float g_fk[BB * KPn * KQn * Tn];
static __device__ float g_fv[BB * KPn * KQn * Tn];
static __device__ float g_obv[BB * KPn * KQn];
static __device__ float g_M[BB * KPn * KQn * Tn];
static __device__ float g_U[BB * KPn * KQn];
static __device__ float g_Gl[BB * KPn * Rn];
static __device__ float g_Gr[BB * KQn * Rn];
static __device__ float g_left[BB * KPn * Rn];
static __device__ float g_right[BB * KQn * Rn];

// ---------------- K0: per-row projections A1/A2 and u1/u2 ----------------
__global__ __launch_bounds__(256) void k0_rowproj(
    const float* __restrict__ Eq, const float* __restrict__ Ep,
    const float* __restrict__ W_in, const float* __restrict__ W_out)
{
    const int b = blockIdx.x;
    const int side = blockIdx.y;   // 0 -> Eq/W1, 1 -> Ep/W2
    const float* src = side ? (Ep + b * KPn * Hn) : (Eq + b * KQn * Hn);
    const int woff = side ? Hn : 0;
    float* A = side ? (g_A2 + b * KPn * Tn) : (g_A1 + b * KQn * Tn);
    float* u = side ? (g_u2 + b * KPn) : (g_u1 + b * KQn);

    __shared__ float sW[Tn][Hn + 1];
    __shared__ float swv[Hn];
    const int tid = threadIdx.y * 32 + threadIdx.x;
    for (int i = tid; i < Tn * Hn; i += 256) {
        int t = i >> 8, h = i & 255;
        sW[t][h] = W_in[t * Rn + woff + h];
    }
    for (int i = tid; i < Hn; i += 256) swv[i] = W_out[woff + i];
    __syncthreads();

    const int t = threadIdx.x;
    for (int y = threadIdx.y; y < 192; y += 8) {
        const float* row = src + y * Hn;
        float acc = 0.f, up = 0.f;
        for (int h = 0; h < Hn; h++) acc += row[h] * sW[t][h];
        for (int h = t; h < Hn; h += 32) up += row[h] * swv[h];
        #pragma unroll
        for (int o = 16; o; o >>= 1) up += __shfl_down_sync(0xffffffffu, up, o);
        A[y * Tn + t] = acc;
        if (t == 0) u[y] = up;
    }
}

// small 32x32 matmul: dst = e1 @ W^T + bias, W row-major [32][32]
__device__ __forceinline__ void small_mm(const float e1[Tn], const float* __restrict__ W,
                                         const float* __restrict__ bias, float* __restrict__ dst)
{
    float4* d = reinterpret_cast<float4*>(dst);
    #pragma unroll
    for (int u4 = 0; u4 < 8; u4++) {
        float r[4];
        #pragma unroll
        for (int uu = 0; uu < 4; uu++) {
            const int u = u4 * 4 + uu;
            float s = bias[u];
            const float4* w4 = reinterpret_cast<const float4*>(W + u * Tn);
            #pragma unroll
            for (int t4 = 0; t4 < 8; t4++) {
                float4 w = w4[t4];
                s += e1[t4 * 4 + 0] * w.x + e1[t4 * 4 + 1] * w.y
                   + e1[t4 * 4 + 2] * w.z + e1[t4 * 4 + 3] * w.w;
            }
            r[uu] = s;
        }
        d[u4] = make_float4(r[0], r[1], r[2], r[3]);
    }
}

// ---------------- K1: per (b,p) pair: bilinear E1 + fq/fk/fv/obv fused ----------------
__global__ __launch_bounds__(192) void k1_pair(
    const float* __restrict__ Eq, const float* __restrict__ Ep,
    const float* __restrict__ W_in,
    const float* __restrict__ Wq, const float* __restrict__ bq,
    const float* __restrict__ Wk, const float* __restrict__ bk,
    const float* __restrict__ Wv, const float* __restrict__ bv,
    const float* __restrict__ Wo1, const float* __restrict__ bo1,
    const float* __restrict__ Wo2, const float* __restrict__ bo2)
{
    const int b = blockIdx.x, p = blockIdx.y;
    __shared__ __align__(16) float sEp[Hn];
    __shared__ __align__(16) float sW3[Tn][Hn];   // W_in[:, 2H:3H]
    __shared__ float sA2[Tn];
    const int tid = threadIdx.x;

    const float* eprow = Ep + (b * KPn + p) * Hn;
    for (int i = tid; i < Hn; i += 192) sEp[i] = eprow[i];
    for (int i = tid; i < Tn; i += 192) sA2[i] = g_A2[(b * KPn + p) * Tn + i];
    for (int i = tid; i < Tn * Hn; i += 192) {
        int t = i >> 8, h = i & 255;
        sW3[t][h] = W_in[t * Rn + 2 * Hn + h];
    }
    __syncthreads();

    const int q = tid;
    float acc[Tn];
    #pragma unroll
    for (int t = 0; t < Tn; t++) acc[t] = 0.f;

    const float4* eq4 = reinterpret_cast<const float4*>(Eq + (b * KQn + q) * Hn);
    const float4* sEp4 = reinterpret_cast<const float4*>(sEp);
    for (int h4 = 0; h4 < Hn / 4; h4++) {
        float4 e = eq4[h4];
        float4 pp = sEp4[h4];
        float4 ev = make_float4(e.x * pp.x, e.y * pp.y, e.z * pp.z, e.w * pp.w);
        #pragma unroll
        for (int t = 0; t < Tn; t++) {
            const float4 w = *reinterpret_cast<const float4*>(&sW3[t][h4 * 4]);
            acc[t] += ev.x * w.x + ev.y * w.y + ev.z * w.z + ev.w * w.w;
        }
    }
    // add A1[b,q,:] + A2[b,p,:]
    const float4* a1 = reinterpret_cast<const float4*>(g_A1 + (b * KQn + q) * Tn);
    #pragma unroll
    for (int t4 = 0; t4 < 8; t4++) {
        float4 a = a1[t4];
        acc[t4 * 4 + 0] += a.x + sA2[t4 * 4 + 0];
        acc[t4 * 4 + 1] += a.y + sA2[t4 * 4 + 1];
        acc[t4 * 4 + 2] += a.z + sA2[t4 * 4 + 2];
        acc[t4 * 4 + 3] += a.w + sA2[t4 * 4 + 3];
    }

    const int pairbase = (b * KPn + p) * KQn + q;
    small_mm(acc, Wq, bq, g_fq + pairbase * Tn);
    small_mm(acc, Wk, bk, g_fk + pairbase * Tn);
    small_mm(acc, Wv, bv, g_fv + pairbase * Tn);

    // obv = sigmoid( relu(E1@Wo1^T+bo1) . Wo2 + bo2 )
    float ob = bo2[0];
    #pragma unroll
    for (int u = 0; u < Tn; u++) {
        float s = bo1[u];
        const float4* w4 = reinterpret_cast<const float4*>(Wo1 + u * Tn);
        #pragma unroll
        for (int t4 = 0; t4 < 8; t4++) {
            float4 w = w4[t4];
            s += acc[t4 * 4 + 0] * w.x + acc[t4 * 4 + 1] * w.y
               + acc[t4 * 4 + 2] * w.z + acc[t4 * 4 + 3] * w.w;
        }
        ob += fmaxf(s, 0.f) * Wo2[u];
    }
    g_obv[pairbase] = 1.f / (1.f + __expf(-ob));
}

// ---------------- K2: horizontal attention (per (b,p)), writes M ----------------
__global__ __launch_bounds__(192) void k2_attn_h(const float* __restrict__ mask)
{
    const int b = blockIdx.x, p = blockIdx.y;
    __shared__ float4 sfk[KQn * 8];
    __shared__ float4 sfv[KQn * 8];
    const int j = threadIdx.x;
    const int base = (b * KPn + p) * KQn;

    const float4* fk4 = reinterpret_cast<const float4*>(g_fk + base * Tn);
    const float4* fv4 = reinterpret_cast<const float4*>(g_fv + base * Tn);
    const float* ob = g_obv + base;
    for (int i = j; i < KQn * 8; i += 192) {
        const int k = i >> 3;
        const float s = SCALEV * ob[k];
        float4 v = fk4[i];
        sfk[i] = make_float4(v.x * s, v.y * s, v.z * s, v.w * s);
        sfv[i] = fv4[i];
    }
    __syncthreads();

    float4 fq[8];
    const float4* fqr = reinterpret_cast<const float4*>(g_fq + (base + j) * Tn);
    #pragma unroll
    for (int i = 0; i < 8; i++) fq[i] = fqr[i];
    const float* mk = mask + base;

    float m = -3.4e38f;
    for (int k = 0; k < KQn; k++) {
        float l = 0.f;
        #pragma unroll
        for (int i = 0; i < 8; i++) {
            float4 w = sfk[k * 8 + i];
            l += fq[i].x * w.x + fq[i].y * w.y + fq[i].z * w.z + fq[i].w * w.w;
        }
        if (mk[k] < 0.5f) l = NEGV;
        m = fmaxf(m, l);
    }
    float s = 0.f;
    float4 acc[8];
    #pragma unroll
    for (int i = 0; i < 8; i++) acc[i] = make_float4(0.f, 0.f, 0.f, 0.f);
    for (int k = 0; k < KQn; k++) {
        float l = 0.f;
        #pragma unroll
        for (int i = 0; i < 8; i++) {
            float4 w = sfk[k * 8 + i];
            l += fq[i].x * w.x + fq[i].y * w.y + fq[i].z * w.z + fq[i].w * w.w;
        }
        if (mk[k] < 0.5f) l = NEGV;
        const float e = __expf(l - m);
        s += e;
        #pragma unroll
        for (int i = 0; i < 8; i++) {
            float4 v = sfv[k * 8 + i];
            acc[i].x += e * v.x; acc[i].y += e * v.y;
            acc[i].z += e * v.z; acc[i].w += e * v.w;
        }
    }
    const float inv = 1.f / s;
    float4* outp = reinterpret_cast<float4*>(g_M + (base + j) * Tn);
    #pragma unroll
    for (int i = 0; i < 8; i++)
        outp[i] = make_float4(acc[i].x * inv, acc[i].y * inv, acc[i].z * inv, acc[i].w * inv);
}

// ---------------- K3: vertical attention (per (b,q)), accumulates into M ----------------
__global__ __launch_bounds__(192) void k3_attn_v(const float* __restrict__ mask)
{
    const int b = blockIdx.x, q = blockIdx.y;
    __shared__ float4 sfk[KPn * 8];
    __shared__ float4 sfv[KPn * 8];
    const int j = threadIdx.x;  // query index over p

    for (int i = j; i < KPn * 8; i += 192) {
        const int k = i >> 3, t4 = i & 7;
        const int ridx = ((b * KPn + k) * KQn + q) * 8 + t4;   // float4 units
        const float s = SCALEV * g_obv[(b * KPn + k) * KQn + q];
        float4 v = reinterpret_cast<const float4*>(g_fk)[ridx];
        sfk[i] = make_float4(v.x * s, v.y * s, v.z * s, v.w * s);
        sfv[i] = reinterpret_cast<const float4*>(g_fv)[ridx];
    }
    __syncthreads();

    float4 fq[8];
    const float4* fqr = reinterpret_cast<const float4*>(g_fq + ((b * KPn + j) * KQn + q) * Tn);
    #pragma unroll
    for (int i = 0; i < 8; i++) fq[i] = fqr[i];

    float m = -3.4e38f;
    for (int k = 0; k < KPn; k++) {
        float l = 0.f;
        #pragma unroll
        for (int i = 0; i < 8; i++) {
            float4 w = sfk[k * 8 + i];
            l += fq[i].x * w.x + fq[i].y * w.y + fq[i].z * w.z + fq[i].w * w.w;
        }
        if (mask[(b * KPn + k) * KQn + q] < 0.5f) l = NEGV;
        m = fmaxf(m, l);
    }
    float s = 0.f;
    float4 acc[8];
    #pragma unroll
    for (int i = 0; i < 8; i++) acc[i] = make_float4(0.f, 0.f, 0.f, 0.f);
    for (int k = 0; k < KPn; k++) {
        float l = 0.f;
        #pragma unroll
        for (int i = 0; i < 8; i++) {
            float4 w = sfk[k * 8 + i];
            l += fq[i].x * w.x + fq[i].y * w.y + fq[i].z * w.z + fq[i].w * w.w;
        }
        if (mask[(b * KPn + k) * KQn + q] < 0.5f) l = NEGV;
        const float e = __expf(l - m);
        s += e;
        #pragma unroll
        for (int i = 0; i < 8; i++) {
            float4 v = sfv[k * 8 + i];
            acc[i].x += e * v.x; acc[i].y += e * v.y;
            acc[i].z += e * v.z; acc[i].w += e * v.w;
        }
    }
    const float inv = 1.f / s;
    float4* outp = reinterpret_cast<float4*>(g_M + ((b * KPn + j) * KQn + q) * Tn);
    #pragma unroll
    for (int i = 0; i < 8; i++) {
        float4 mm = outp[i];
        outp[i] = make_float4(mm.x + acc[i].x * inv, mm.y + acc[i].y * inv,
                              mm.z + acc[i].z * inv, mm.w + acc[i].w * inv);
    }
}

// ---------------- K4: U = u1 + u2 + bilinear(w3) + M.w4, masked ----------------
__global__ __launch_bounds__(192) void k4_U(
    const float* __restrict__ Eq, const float* __restrict__ Ep,
    const float* __restrict__ W_out, const float* __restrict__ mask)
{
    const int b = blockIdx.x, p = blockIdx.y, q = threadIdx.x;
    __shared__ __align__(16) float sEpw[Hn];
    __shared__ __align__(16) float sw4[Tn];
    for (int i = q; i < Hn; i += 192) sEpw[i] = Ep[(b * KPn + p) * Hn + i] * W_out[2 * Hn + i];
    for (int i = q; i < Tn; i += 192) sw4[i] = W_out[Rn + i];
    __syncthreads();

    const float4* eq4 = reinterpret_cast<const float4*>(Eq + (b * KQn + q) * Hn);
    const float4* ew4 = reinterpret_cast<const float4*>(sEpw);
    float u3 = 0.f;
    for (int h4 = 0; h4 < Hn / 4; h4++) {
        float4 e = eq4[h4], w = ew4[h4];
        u3 += e.x * w.x + e.y * w.y + e.z * w.z + e.w * w.w;
    }
    const float4* m4 = reinterpret_cast<const float4*>(g_M + ((b * KPn + p) * KQn + q) * Tn);
    const float4* w44 = reinterpret_cast<const float4*>(sw4);
    float um = 0.f;
    #pragma unroll
    for (int t4 = 0; t4 < 8; t4++) {
        float4 mm = m4[t4], w = w44[t4];
        um += mm.x * w.x + mm.y * w.y + mm.z * w.z + mm.w * w.w;
    }
    const int idx = (b * KPn + p) * KQn + q;
    float Uv = g_u1[b * KQn + q] + g_u2[b * KPn + p] + u3 + um;
    if (mask[idx] < 0.5f) Uv = NEGV;
    g_U[idx] = Uv;
}

// ---------------- K5a: softmax over q (rows of U) -> A''_p, build G_left ----------------
__global__ __launch_bounds__(256) void k5_rowsoft(const float* __restrict__ Eq, const float* __restrict__ Ep)
{
    const int b = blockIdx.x, p = blockIdx.y;
    __shared__ float sw[KQn];
    __shared__ float red[256];
    const int tid = threadIdx.x;
    const int base = (b * KPn + p) * KQn;

    float v = (tid < KQn) ? g_U[base + tid] : -3.4e38f;
    red[tid] = v; __syncthreads();
    for (int o = 128; o; o >>= 1) { if (tid < o) red[tid] = fmaxf(red[tid], red[tid + o]); __syncthreads(); }
    const float m = red[0]; __syncthreads();
    const float e = (tid < KQn) ? __expf(v - m) : 0.f;
    red[tid] = e; __syncthreads();
    for (int o = 128; o; o >>= 1) { if (tid < o) red[tid] += red[tid + o]; __syncthreads(); }
    const float inv = 1.f / red[0];
    if (tid < KQn) sw[tid] = e * inv;
    __syncthreads();

    const int h = tid;  // 0..255
    float a = 0.f;
    for (int k = 0; k < KQn; k++) a += sw[k] * Eq[(b * KQn + k) * Hn + h];
    const float ep = Ep[(b * KPn + p) * Hn + h];
    float* G = g_Gl + (b * KPn + p) * Rn;
    G[h] = ep; G[Hn + h] = a; G[2 * Hn + h] = ep * a;
}

// ---------------- K5b: softmax over p (cols of U) -> B''_p, build G_right ----------------
__global__ __launch_bounds__(256) void k5_colsoft(const float* __restrict__ Eq, const float* __restrict__ Ep)
{
    const int b = blockIdx.x, q = blockIdx.y;
    __shared__ float sw[KPn];
    __shared__ float red[256];
    const int tid = threadIdx.x;

    float v = (tid < KPn) ? g_U[(b * KPn + tid) * KQn + q] : -3.4e38f;
    red[tid] = v; __syncthreads();
    for (int o = 128; o; o >>= 1) { if (tid < o) red[tid] = fmaxf(red[tid], red[tid + o]); __syncthreads(); }
    const float m = red[0]; __syncthreads();
    const float e = (tid < KPn) ? __expf(v - m) : 0.f;
    red[tid] = e; __syncthreads();
    for (int o = 128; o; o >>= 1) { if (tid < o) red[tid] += red[tid + o]; __syncthreads(); }
    const float inv = 1.f / red[0];
    if (tid < KPn) sw[tid] = e * inv;
    __syncthreads();

    const int h = tid;
    float a = 0.f;
    for (int k = 0; k < KPn; k++) a += sw[k] * Ep[(b * KPn + k) * Hn + h];
    const float eq = Eq[(b * KQn + q) * Hn + h];
    float* G = g_Gr + (b * KQn + q) * Rn;
    G[h] = eq; G[Hn + h] = a; G[2 * Hn + h] = eq * a;
}

// ---------------- K6: gates: out = sigmoid(G@W^T + b) * G   (tiled 64x64 GEMM) ----------------
__global__ __launch_bounds__(256) void k6_gate(
    const float* __restrict__ Wl, const float* __restrict__ bl,
    const float* __restrict__ Wr, const float* __restrict__ br)
{
    const int side = blockIdx.z;
    const float* __restrict__ G = side ? g_Gr : g_Gl;
    const float* __restrict__ W = side ? Wr : Wl;
    const float* __restrict__ bias = side ? br : bl;
    float* __restrict__ outp = side ? g_right : g_left;
    const int row0 = blockIdx.y * 64;
    const int col0 = blockIdx.x * 64;
    __shared__ float sA[64][17];
    __shared__ float sB[64][17];
    const int tid = threadIdx.x;
    const int tx = tid & 15, ty = tid >> 4;
    const int lr = tid >> 2, lk = (tid & 3) * 4;
    float c[4][4] = {};

    for (int kc = 0; kc < Rn; kc += 16) {
        float4 av = *reinterpret_cast<const float4*>(G + (row0 + lr) * Rn + kc + lk);
        float4 bv = *reinterpret_cast<const float4*>(W + (col0 + lr) * Rn + kc + lk);
        __syncthreads();
        sA[lr][lk] = av.x; sA[lr][lk + 1] = av.y; sA[lr][lk + 2] = av.z; sA[lr][lk + 3] = av.w;
        sB[lr][lk] = bv.x; sB[lr][lk + 1] = bv.y; sB[lr][lk + 2] = bv.z; sB[lr][lk + 3] = bv.w;
        __syncthreads();
        #pragma unroll
        for (int kk = 0; kk < 16; kk++) {
            float a[4], bb2[4];
            #pragma unroll
            for (int i = 0; i < 4; i++) a[i] = sA[ty + 16 * i][kk];
            #pragma unroll
            for (int i = 0; i < 4; i++) bb2[i] = sB[tx + 16 * i][kk];
            #pragma unroll
            for (int i = 0; i < 4; i++)
                #pragma unroll
                for (int jj = 0; jj < 4; jj++) c[i][jj] += a[i] * bb2[jj];
        }
    }
    #pragma unroll
    for (int i = 0; i < 4; i++) {
        const int r = row0 + ty + 16 * i;
        #pragma unroll
        for (int jj = 0; jj < 4; jj++) {
            const int cc = col0 + tx + 16 * jj;
            const float g = G[r * Rn + cc];
            const float s = 1.f / (1.f + __expf(-(c[i][jj] + bias[cc])));
            outp[r * Rn + cc] = s * g;
        }
    }
}

// ---------------- K7: out[b,p,q] = relu(left[b,p,:].right[b,q,:]) ----------------
__global__ __launch_bounds__(256) void k7_final(float* __restrict__ outp)
{
    const int b = blockIdx.z;
    const float* __restrict__ A = g_left + b * KPn * Rn;
    const float* __restrict__ Bm = g_right + b * KQn * Rn;
    const int row0 = blockIdx.y * 64;
    const int col0 = blockIdx.x * 64;
    __shared__ float sA[64][17];
    __shared__ float sB[64][17];
    const int tid = threadIdx.x;
    const int tx = tid & 15, ty = tid >> 4;
    const int lr = tid >> 2, lk = (tid & 3) * 4;
    float c[4][4] = {};

    for (int kc = 0; kc < Rn; kc += 16) {
        float4 av = *reinterpret_cast<const float4*>(A + (row0 + lr) * Rn + kc + lk);
        float4 bv = *reinterpret_cast<const float4*>(Bm + (col0 + lr) * Rn + kc + lk);
        __syncthreads();
        sA[lr][lk] = av.x; sA[lr][lk + 1] = av.y; sA[lr][lk + 2] = av.z; sA[lr][lk + 3] = av.w;
        sB[lr][lk] = bv.x; sB[lr][lk + 1] = bv.y; sB[lr][lk + 2] = bv.z; sB[lr][lk + 3] = bv.w;
        __syncthreads();
        #pragma unroll
        for (int kk = 0; kk < 16; kk++) {
            float a[4], bb2[4];
            #pragma unroll
            for (int i = 0; i < 4; i++) a[i] = sA[ty + 16 * i][kk];
            #pragma unroll
            for (int i = 0; i < 4; i++) bb2[i] = sB[tx + 16 * i][kk];
            #pragma unroll
            for (int i = 0; i < 4; i++)
                #pragma unroll
                for (int jj = 0; jj < 4; jj++) c[i][jj] += a[i] * bb2[jj];
        }
    }
    #pragma unroll
    for (int i = 0; i < 4; i++) {
        const int r = row0 + ty + 16 * i;
        #pragma unroll
        for (int jj = 0; jj < 4; jj++) {
            const int cc = col0 + tx + 16 * jj;
            outp[b * KPn * KQn + r * KQn + cc] = fmaxf(c[i][jj], 0.f);
        }
    }
}

// ---------------- launch ----------------
extern "C" void kernel_launch(void* const* d_in, const int* in_sizes, int n_in,
                              void* d_out, int out_size)
{
    const float* Eq    = (const float*)d_in[0];
    const float* Ep    = (const float*)d_in[1];
    const float* mask  = (const float*)d_in[2];
    const float* W_in  = (const float*)d_in[3];
    const float* Wq    = (const float*)d_in[4];
    const float* bq    = (const float*)d_in[5];
    const float* Wk    = (const float*)d_in[6];
    const float* bk    = (const float*)d_in[7];
    const float* Wv    = (const float*)d_in[8];
    const float* bv    = (const float*)d_in[9];
    const float* Wo1   = (const float*)d_in[10];
    const float* bo1   = (const float*)d_in[11];
    const float* Wo2   = (const float*)d_in[12];
    const float* bo2   = (const float*)d_in[13];
    const float* W_out = (const float*)d_in[14];
    const float* Wl    = (const float*)d_in[15];
    const float* bl    = (const float*)d_in[16];
    const float* Wr    = (const float*)d_in[17];
    const float* br    = (const float*)d_in[18];
    float* outp = (float*)d_out;

    k0_rowproj<<<dim3(BB, 2), dim3(32, 8)>>>(Eq, Ep, W_in, W_out);
    k1_pair<<<dim3(BB, KPn), 192>>>(Eq, Ep, W_in, Wq, bq, Wk, bk, Wv, bv, Wo1, bo1, Wo2, bo2);
    k2_attn_h<<<dim3(BB, KPn), 192>>>(mask);
    k3_attn_v<<<dim3(BB, KQn), 192>>>(mask);
    k4_U<<<dim3(BB, KPn), 192>>>(Eq, Ep, W_out, mask);
    k5_rowsoft<<<dim3(BB, KPn), 256>>>(Eq, Ep);
    k5_colsoft<<<dim3(BB, KQn), 256>>>(Eq, Ep);
    k6_gate<<<dim3(12, 12, 2), 256>>>(Wl, bl, Wr, br);
    k7_final<<<dim3(3, 3, BB), 256>>>(outp);
}